// round 11
// baseline (speedup 1.0000x reference)
#include <cuda_runtime.h>
#include <cstddef>

// Problem constants (from reference setup_inputs)
#define TT   1000
#define BB   8192
#define IN   4
#define HID  10
#define OUT  3
#define BETA 0.95f
#define THR  1.0f

#define NLUT (1 << HID)      // 1024 possible spk1 patterns
#define B3   (BB * OUT)      // floats per timestep per output array
#define QPT  4               // threads per batch element
#define SLOTS 3              // layer-1 units per thread (uniform; lanes 2,3 have a dummy)

// Four threads per batch element. 128 blocks x 256 threads = 32768 threads
// = 1024 warps. Lane q of each element owns hidden units:
//   q0: 0,1,2   q1: 3,4,5   q2: 6,7(+dummy)   q3: 8,9(+dummy)
// Masks combined via shfl_xor(1) then shfl_xor(2). Lane q<3 owns layer-2
// unit q and writes its spk+mem pair.
__global__ __launch_bounds__(256, 1)
void snn_lif_kernel(const float* __restrict__ x,
                    const float* __restrict__ W1,
                    const float* __restrict__ b1,
                    const float* __restrict__ W2,
                    const float* __restrict__ b2,
                    float* __restrict__ out)
{
    // LUT: cur2 = W2 @ spk1 + b2 for every possible spk1 bitmask.
    // Ascending-h subset sum, separately-rounded adds, bias last —
    // bit-identical to the reference 0/1 dot under fma OR mul+add lowering.
    __shared__ float4 lut[NLUT];
    for (int m = threadIdx.x; m < NLUT; m += blockDim.x) {
        float c0 = 0.f, c1 = 0.f, c2 = 0.f;
        #pragma unroll
        for (int h = 0; h < HID; ++h) {
            if (m & (1 << h)) {
                c0 = __fadd_rn(c0, W2[0 * HID + h]);
                c1 = __fadd_rn(c1, W2[1 * HID + h]);
                c2 = __fadd_rn(c2, W2[2 * HID + h]);
            }
        }
        c0 = __fadd_rn(c0, b2[0]);
        c1 = __fadd_rn(c1, b2[1]);
        c2 = __fadd_rn(c2, b2[2]);
        lut[m] = make_float4(c0, c1, c2, 0.f);
    }

    const int tid   = blockIdx.x * blockDim.x + threadIdx.x;
    const int e     = tid >> 2;               // batch element
    const int q     = tid & 3;                // lane role within element
    const int hbase = (q < 2) ? 3 * q : 2 * q + 2;   // 0,3,6,8
    const int nu    = (q < 2) ? 3 : 2;        // real units in this lane

    // This lane's layer-1 weights (dummy slot = all zeros -> never spikes).
    float w1[SLOTS][IN], bb1[SLOTS];
    #pragma unroll
    for (int j = 0; j < SLOTS; ++j) {
        const bool real = (j < nu);
        bb1[j] = real ? b1[hbase + j] : 0.0f;
        #pragma unroll
        for (int i = 0; i < IN; ++i)
            w1[j][i] = real ? W1[(hbase + j) * IN + i] : 0.0f;
    }
    __syncthreads();

    // State: membranes + prev-spike as float in {-1, 0} (reset is a plain
    // always-executed add; adding -0.0f is the identity => bit-exact).
    float m1[SLOTS], s1[SLOTS];
    #pragma unroll
    for (int j = 0; j < SLOTS; ++j) { m1[j] = 0.f; s1[j] = 0.f; }
    float m2 = 0.f, s2 = 0.f;                 // layer-2 unit q (q<3)

    const float4* __restrict__ xp = reinterpret_cast<const float4*>(x) + e;
    // Lane q<3 writes spk2[t,e,q] and mem2[t,e,q].
    float* __restrict__ ps = out + (size_t)e * OUT + q;                   // spk2
    float* __restrict__ pm = out + (size_t)TT * B3 + (size_t)e * OUT + q; // mem2

    // Prefetch ring: x[t..t+3] resident.
    float4 xbuf[4];
    #pragma unroll
    for (int k = 0; k < 4; ++k) xbuf[k] = xp[(size_t)k * BB];

    // Layer-1 for one step: updates m1/s1, returns this lane's mask bits.
    auto layer1 = [&](const float4 xv) -> unsigned {
        unsigned mk = 0;
        #pragma unroll
        for (int j = 0; j < SLOTS; ++j) {
            // Ascending-k, separate mul/add roundings (no fma), bias last.
            float c = __fmul_rn(xv.x, w1[j][0]);
            c = __fadd_rn(c, __fmul_rn(xv.y, w1[j][1]));
            c = __fadd_rn(c, __fmul_rn(xv.z, w1[j][2]));
            c = __fadd_rn(c, __fmul_rn(xv.w, w1[j][3]));
            c = __fadd_rn(c, bb1[j]);
            float m = __fadd_rn(__fmul_rn(BETA, m1[j]), c); // beta*mem + cur
            m = __fadd_rn(m, s1[j]);                         // + (-reset*THR)
            const bool sp = m > THR;                         // dummy: always false
            s1[j] = sp ? -1.0f : 0.0f;
            mk |= (sp ? (1u << (hbase + j)) : 0u);
            m1[j] = m;
        }
        return mk;
    };

    // Pipeline prologue: layer-1 of step 0.
    unsigned myMask = layer1(xbuf[0]);

    for (int t = 0; t < TT; t += 4) {
        // Prefetch x[t+4..t+7] (tail clamps to x[0..3]; feeds only the
        // discarded junk layer-1 past step TT-1).
        const float4* xq = (t + 4 < TT) ? (xp + (size_t)(t + 4) * BB) : xp;
        float4 nxt[4];
        #pragma unroll
        for (int k = 0; k < 4; ++k) nxt[k] = xq[(size_t)k * BB];

        #pragma unroll
        for (int k = 0; k < 4; ++k) {
            // ---- step t+k: butterfly the 4 lane-masks (latency in flight) --
            unsigned fm = myMask;
            fm |= __shfl_xor_sync(0xFFFFFFFFu, fm, 1);
            fm |= __shfl_xor_sync(0xFFFFFFFFu, fm, 2);

            // ---- layer-1 of step t+k+1 overlaps the shfl/LDS latency ----
            const float4 xnext = (k < 3) ? xbuf[k + 1] : nxt[0];
            const unsigned newMask = layer1(xnext);

            // ---- layer-2 of step t+k: this lane's output unit only ----
            const float4 cv = lut[fm];
            const float cc = (q == 0) ? cv.x : ((q == 1) ? cv.y : cv.z);
            float m = __fadd_rn(__fmul_rn(BETA, m2), cc);
            m = __fadd_rn(m, s2);
            const bool sp = m > THR;
            s2 = sp ? -1.0f : 0.0f;
            m2 = m;
            if (q < 3) {
                const size_t off = (size_t)(t + k) * B3;
                ps[off] = sp ? 1.0f : 0.0f;   // spk2_rec[t+k, e, q]
                pm[off] = m;                   // mem2_rec[t+k, e, q]
            }

            myMask = newMask;
        }

        #pragma unroll
        for (int k = 0; k < 4; ++k) xbuf[k] = nxt[k];
    }
}

extern "C" void kernel_launch(void* const* d_in, const int* in_sizes, int n_in,
                              void* d_out, int out_size)
{
    const float* x  = (const float*)d_in[0];   // [1000, 8192, 4]
    const float* W1 = (const float*)d_in[1];   // [10, 4]
    const float* b1 = (const float*)d_in[2];   // [10]
    const float* W2 = (const float*)d_in[3];   // [3, 10]
    const float* b2 = (const float*)d_in[4];   // [3]
    float* out = (float*)d_out;                // [spk2_rec | mem2_rec]

    snn_lif_kernel<<<(BB * QPT) / 256, 256>>>(x, W1, b1, W2, b2, out);
}